// round 1
// baseline (speedup 1.0000x reference)
#include <cuda_runtime.h>

// Reference analysis:
//   d = softmax(dense(weighted), axis=-1) where dense output has last dim == 1.
//   softmax over a size-1 axis is identically 1.0 (exp(x-x)/exp(x-x)).
//   out = sigmoid(1.0) = 0.7310585786300049 for every (b, t).
// The output is a constant tensor independent of all inputs, so the optimal
// kernel writes that constant to d_out (B*T = 32768 fp32 elements).

static constexpr float SIGMOID_ONE = 0.73105857863000487925f; // 1/(1+exp(-1))

__global__ void AttentionRNNLayer_87677462380995_kernel(float* __restrict__ out, int n) {
    // Vectorized fill: n is 32768 (divisible by 4), but guard anyway.
    int n4 = n >> 2;
    float4 v = make_float4(SIGMOID_ONE, SIGMOID_ONE, SIGMOID_ONE, SIGMOID_ONE);
    float4* __restrict__ out4 = reinterpret_cast<float4*>(out);
    for (int i = blockIdx.x * blockDim.x + threadIdx.x; i < n4;
         i += gridDim.x * blockDim.x) {
        out4[i] = v;
    }
    // Tail (n % 4 != 0) — not expected here, but correct in general.
    int tail_start = n4 << 2;
    int idx = tail_start + blockIdx.x * blockDim.x + threadIdx.x;
    if (idx < n) out[idx] = SIGMOID_ONE;
}

extern "C" void kernel_launch(void* const* d_in, const int* in_sizes, int n_in,
                              void* d_out, int out_size) {
    (void)d_in; (void)in_sizes; (void)n_in;
    float* out = reinterpret_cast<float*>(d_out);
    // 32768 elements -> 8192 float4 stores. 32 blocks x 256 threads covers it
    // in one pass with full coalescing.
    int threads = 256;
    int n4 = out_size >> 2;
    int blocks = (n4 + threads - 1) / threads;
    if (blocks < 1) blocks = 1;
    if (blocks > 1024) blocks = 1024;
    AttentionRNNLayer_87677462380995_kernel<<<blocks, threads>>>(out, out_size);
}

// round 2
// speedup vs baseline: 1.0486x; 1.0486x over previous
#include <cuda_runtime.h>

// Reference analysis (verified: rel_err == 0.0 in R1):
//   d = softmax(dense(weighted), axis=-1) with last dim == 1 -> identically 1.0.
//   out = sigmoid(1.0) = 0.7310585786300049 for every (b, t).
// Output is a constant (64, 512) fp32 tensor; optimal kernel is a minimal fill.
//
// R1 showed we are at the launch/drain floor (DRAM 0.0%). This version strips
// the grid-stride loop and tail epilogue: straight-line body, one predicated
// STG.128 per thread.

static constexpr float SIGMOID_ONE = 0.73105857863000487925f; // 1/(1+exp(-1))

__global__ void __launch_bounds__(128, 1)
AttentionRNNLayer_87677462380995_kernel(float4* __restrict__ out4, int n4) {
    int i = blockIdx.x * blockDim.x + threadIdx.x;
    if (i < n4) {
        out4[i] = make_float4(SIGMOID_ONE, SIGMOID_ONE, SIGMOID_ONE, SIGMOID_ONE);
    }
}

extern "C" void kernel_launch(void* const* d_in, const int* in_sizes, int n_in,
                              void* d_out, int out_size) {
    (void)d_in; (void)in_sizes; (void)n_in;
    // out_size = 32768 fp32 = 8192 float4 stores; one store per thread.
    int n4 = out_size >> 2;                 // 8192
    int threads = 128;
    int blocks = (n4 + threads - 1) / threads;  // 64
    AttentionRNNLayer_87677462380995_kernel<<<blocks, threads>>>(
        reinterpret_cast<float4*>(d_out), n4);
    // Tail elements (out_size % 4) don't exist for this problem (32768 % 4 == 0).
}